// round 12
// baseline (speedup 1.0000x reference)
#include <cuda_runtime.h>
#include <cuda_bf16.h>
#include <cstdint>

// VectorQuantizer: z[16,256,32,32] fp32, codebook[16384,256] fp32
// out: z_q [16,32,32,256] flattened (4,194,304 floats) then idx (16384) as float.

#define NROWS 16384
#define KCODES 16384
#define NZQ (16384*256)
#define KCAND 64
#define WINDOW 2.0e-4f

typedef unsigned int uint;

// ---- scratch (device globals; no allocation allowed) ----
__device__ float4        g_zt4[NROWS * 64];      // z transposed [N][256] fp32, 16 MB
__device__ float         g_zn2[NROWS];
__device__ float         g_ce[KCODES];
__device__ int           g_idx[NROWS];
__device__ __nv_bfloat16 g_zbf[NROWS * 256];     // bf16, ldmatrix-swizzle baked, 8 MB
__device__ __nv_bfloat16 g_cbbf[KCODES * 256];   // bf16, ldmatrix-swizzle baked, 8 MB
__device__ int           g_cand[NROWS * KCAND];  // 4 MB
__device__ int           g_ccnt[NROWS];

// =====================================================================
// helpers (baseline sm_90 PTX only: compiles under compute_103 virtual)
// =====================================================================
__device__ __forceinline__ uint smem_u32(const void* p) {
    uint a;
    asm("{ .reg .u64 t; cvta.to.shared.u64 t, %1; cvt.u32.u64 %0, t; }"
        : "=r"(a) : "l"(p));
    return a;
}
__device__ __forceinline__ void mbar_init(uint addr, uint cnt) {
    asm volatile("mbarrier.init.shared.b64 [%0], %1;" :: "r"(addr), "r"(cnt) : "memory");
}
__device__ __forceinline__ void mbar_expect_tx(uint addr, uint tx) {
    asm volatile("mbarrier.arrive.expect_tx.shared.b64 _, [%0], %1;"
                 :: "r"(addr), "r"(tx) : "memory");
}
__device__ __forceinline__ void mbar_wait(uint addr, uint parity) {
    asm volatile("{\n\t.reg .pred P;\n\t"
                 "WL_%=:\n\t"
                 "mbarrier.try_wait.parity.acquire.cta.shared::cta.b64 P, [%0], %1, 0x989680;\n\t"
                 "@P bra WD_%=;\n\t"
                 "bra WL_%=;\n\t"
                 "WD_%=:\n\t}"
                 :: "r"(addr), "r"(parity) : "memory");
}
// 1D bulk copy gmem->smem, completion via mbarrier complete_tx
__device__ __forceinline__ void bulkcp(uint dst, const void* src, uint bytes,
                                       uint mbar) {
    asm volatile(
        "cp.async.bulk.shared::cluster.global.mbarrier::complete_tx::bytes "
        "[%0], [%1], %2, [%3];"
        :: "r"(dst), "l"(src), "r"(bytes), "r"(mbar) : "memory");
}
__device__ __forceinline__ void ldsm4(uint& r0, uint& r1, uint& r2, uint& r3,
                                      uint addr) {
    asm volatile("ldmatrix.sync.aligned.m8n8.x4.shared.b16 {%0,%1,%2,%3}, [%4];"
                 : "=r"(r0), "=r"(r1), "=r"(r2), "=r"(r3) : "r"(addr));
}
__device__ __forceinline__ void mma16816(float* c, const uint* a, const uint* b) {
    asm volatile("mma.sync.aligned.m16n8k16.row.col.f32.bf16.bf16.f32 "
                 "{%0,%1,%2,%3}, {%4,%5,%6,%7}, {%8,%9}, {%0,%1,%2,%3};"
                 : "+f"(c[0]), "+f"(c[1]), "+f"(c[2]), "+f"(c[3])
                 : "r"(a[0]), "r"(a[1]), "r"(a[2]), "r"(a[3]),
                   "r"(b[0]), "r"(b[1]));
}

// =====================================================================
// launch #1: transpose z [B=16, C=256, HW=1024] -> zt [n = b*1024+hw][c]
// =====================================================================
__global__ void k_transpose(const float* __restrict__ z) {
    __shared__ float t[32][33];
    int b = blockIdx.z, c0 = blockIdx.y * 32, hw0 = blockIdx.x * 32;
    float* zt = (float*)g_zt4;
#pragma unroll
    for (int r = 0; r < 4; r++) {
        int c = c0 + threadIdx.y + 8 * r;
        t[threadIdx.y + 8 * r][threadIdx.x] =
            z[((size_t)(b * 256 + c)) * 1024 + hw0 + threadIdx.x];
    }
    __syncthreads();
#pragma unroll
    for (int r = 0; r < 4; r++) {
        int hw = hw0 + threadIdx.y + 8 * r;
        zt[((size_t)(b * 1024 + hw)) * 256 + c0 + threadIdx.x] =
            t[threadIdx.x][threadIdx.y + 8 * r];
    }
}

// =====================================================================
// launch #2: both row-norm sets. rounded multiply + strictly sequential
// fp32 adds (XLA reduce semantics). blocks [0,512): z ; [512,1024): cb
// =====================================================================
__global__ void k_prep_norm(const float* __restrict__ cb) {
    __shared__ float s[32 * 257];
    const int zpart = blockIdx.x < 512;
    const int base = (zpart ? blockIdx.x : blockIdx.x - 512) * 32;
    const float* src = zpart ? (const float*)g_zt4 : cb;
    float* dst = zpart ? g_zn2 : g_ce;
    for (int off = threadIdx.x; off < 32 * 256; off += 256) {
        int r = off >> 8, d = off & 255;
        s[r * 257 + d] = src[(size_t)base * 256 + off];
    }
    __syncthreads();
    if (threadIdx.x < 32) {
        const float* row = &s[threadIdx.x * 257];
        float a = 0.f;
        for (int d = 0; d < 256; ++d) {
            float v = row[d];
            a = __fadd_rn(a, __fmul_rn(v, v));
        }
        dst[base + threadIdx.x] = a;
    }
}

// =====================================================================
// launch #3: fp32 -> bf16 with the ldmatrix XOR swizzle BAKED into gmem:
// 16B chunk ci of row c lands at byte  c*512 + ((ci ^ (c&7)) << 4).
// A 64-row-aligned block of this layout is bit-identical to the smem
// tile the MMA kernel wants, so one cp.async.bulk per tile suffices.
// blocks [0,2048): z ; [2048,4096): codebook (+ zero cand counters)
// =====================================================================
__device__ __forceinline__ uint packbf(float x, float y) {
    __nv_bfloat162 h = __floats2bfloat162_rn(x, y);
    return *reinterpret_cast<uint*>(&h);
}
__global__ void k_prep_bf16(const float4* __restrict__ cb) {
    const int zpart = blockIdx.x < 2048;
    int t = (zpart ? blockIdx.x : blockIdx.x - 2048) * 256 + threadIdx.x;
    const float4* src = zpart ? g_zt4 : cb;
    float4 a = src[2 * t], b = src[2 * t + 1];
    uint4 o;
    o.x = packbf(a.x, a.y); o.y = packbf(a.z, a.w);
    o.z = packbf(b.x, b.y); o.w = packbf(b.z, b.w);
    int c = t >> 5, ci = t & 31;
    size_t addr = (size_t)c * 512 + (uint)((ci ^ (c & 7)) << 4);
    *(uint4*)((char*)(zpart ? g_zbf : g_cbbf) + addr) = o;
    if (!zpart && blockIdx.x < 2048 + 64)
        g_ccnt[(blockIdx.x - 2048) * 256 + threadIdx.x] = 0;  // re-zeroed per replay
}

// =====================================================================
// launch #4: bf16 mma.sync GEMM + approx argmin + candidate collection.
//
// grid 128 = 64 M-blocks x 2 N-halves. 1024 threads, 32 warps
// (8 per SMSP for latency hiding; occ was the binding constraint at 16).
// warpM = wid>>1 (16), warpN = wid&1 (2); warp tile 16 rows x 32 codes
// via m16n8k16 (1 mfrag x 4 nfrag, 16 acc regs -> fits the 64-reg cap
// of 1024 thr/CTA). ce is __ldg'd in the epilogue (not held in regs
// across the mainloop).
// A (256x256 bf16 = 128 KB) resident via ONE cp.async.bulk; B tiles
// (64 codes x 256 d = 32 KB) double-buffered, ONE bulk copy per tile.
// Swizzle pre-baked in gmem; ldmatrix addressing conflict-free.
// Scores are >0 (~256) so float-bits atomicMin on uint is order-safe.
// Tile 0 runs a min-only warm pass; the true argmin always satisfies
// s* <= running min, so it is appended regardless of atomic timing.
// =====================================================================
#define SM_A   0u
#define SM_B   131072u
#define SM_MIN 196608u
#define SM_BAR 197632u
#define SMEM_BYTES 197664

__global__ __launch_bounds__(1024, 1) void k_mma_argmin() {
    extern __shared__ char smem[];
    const uint sb = smem_u32(smem);
    uint* s_minu = (uint*)(smem + SM_MIN);
    const int tid = threadIdx.x, lane = tid & 31, wid = tid >> 5;
    const int warpM = wid >> 1, warpN = wid & 1;
    const int mblk = blockIdx.x >> 1, nhalf = blockIdx.x & 1;
    const int rowbase = mblk * 256, codebase0 = nhalf * 8192;

    const uint mbA = sb + SM_BAR, mbB = sb + SM_BAR + 8;  // mbB[2] at +8,+16

    if (tid == 0) {
        mbar_init(mbA, 1);
        mbar_init(mbB, 1);
        mbar_init(mbB + 8, 1);
    }
    if (tid < 256) s_minu[tid] = 0x7f800000u;
    __syncthreads();
    if (tid == 0) {
        mbar_expect_tx(mbA, 131072u);
        bulkcp(sb + SM_A, (const char*)g_zbf + (size_t)rowbase * 512, 131072u, mbA);
        mbar_expect_tx(mbB, 32768u);
        bulkcp(sb + SM_B, (const char*)g_cbbf + (size_t)codebase0 * 512, 32768u, mbB);
        mbar_expect_tx(mbB + 8, 32768u);
        bulkcp(sb + SM_B + 32768u,
               (const char*)g_cbbf + (size_t)(codebase0 + 64) * 512, 32768u, mbB + 8);
    }

    // ldmatrix address precompute (same swizzled layout as before)
    const int rowA = (lane & 7) + ((lane >> 3) & 1) * 8;
    const int aK = lane >> 4;
    const int rA = warpM * 16 + rowA;
    const uint aAddr = sb + SM_A + (uint)rA * 512u;
    const int aSw = rA & 7;

    const int rowB = (lane & 7) + (lane >> 4) * 8;
    const int bK = (lane >> 3) & 1;
    const int nA = warpN * 32 + rowB, nB = nA + 16;
    const uint bOff0 = (uint)nA * 512u; const int bSw0 = nA & 7;
    const uint bOff1 = (uint)nB * 512u; const int bSw1 = nB & 7;

    float zn2r[2];
#pragma unroll
    for (int h = 0; h < 2; h++)
        zn2r[h] = g_zn2[rowbase + warpM * 16 + (lane >> 2) + 8 * h];
    const int colq = warpN * 32 + (lane & 3) * 2;

    mbar_wait(mbA, 0);   // A resident (also orders s_minu init via earlier sync)

    for (int kt = 0; kt < 128; ++kt) {
        const int buf = kt & 1;
        mbar_wait(mbB + 8u * buf, (kt >> 1) & 1);

        const int ctile = codebase0 + kt * 64;

        float acc[4][4];
#pragma unroll
        for (int nf = 0; nf < 4; nf++)
#pragma unroll
            for (int v = 0; v < 4; v++) acc[nf][v] = 0.f;

        const uint bb = sb + SM_B + (uint)buf * 32768u;
#pragma unroll
        for (int ks = 0; ks < 16; ++ks) {
            uint b0[4], b1[4], a[4];
            ldsm4(b0[0], b0[1], b0[2], b0[3],
                  bb + bOff0 + (uint)(((2 * ks + bK) ^ bSw0) << 4));
            ldsm4(b1[0], b1[1], b1[2], b1[3],
                  bb + bOff1 + (uint)(((2 * ks + bK) ^ bSw1) << 4));
            ldsm4(a[0], a[1], a[2], a[3],
                  aAddr + (uint)(((2 * ks + aK) ^ aSw) << 4));
            mma16816(acc[0], a, b0);
            mma16816(acc[1], a, b0 + 2);
            mma16816(acc[2], a, b1);
            mma16816(acc[3], a, b1 + 2);
        }

        // epilogue: tile 0 gets a min-only warm pass (pass 0) first
        float ce_r[8];
#pragma unroll
        for (int nf = 0; nf < 4; nf++)
#pragma unroll
            for (int q = 0; q < 2; q++)
                ce_r[nf * 2 + q] = __ldg(&g_ce[ctile + colq + nf * 8 + q]);

        for (int pass = (kt == 0 ? 0 : 1); pass < 2; ++pass) {
#pragma unroll
            for (int h = 0; h < 2; h++) {
                const int rl = warpM * 16 + (lane >> 2) + 8 * h;
                const float zn = zn2r[h];
                float m = __uint_as_float(s_minu[rl]);
#pragma unroll
                for (int nf = 0; nf < 4; nf++)
#pragma unroll
                    for (int q = 0; q < 2; q++) {
                        float s = __fmaf_rn(-2.f, acc[nf][h * 2 + q],
                                            __fadd_rn(zn, ce_r[nf * 2 + q]));
                        if (s < m + WINDOW) {
                            atomicMin(&s_minu[rl], __float_as_uint(s));
                            if (pass) {
                                int pos = atomicAdd(&g_ccnt[rowbase + rl], 1);
                                if (pos < KCAND)
                                    g_cand[(rowbase + rl) * KCAND + pos] =
                                        ctile + colq + nf * 8 + q;
                            }
                            if (s < m) m = s;
                        }
                    }
            }
            if (kt == 0 && pass == 0) __syncthreads();
        }

        __syncthreads();   // all warps done reading buf before refill
        if (tid == 0 && kt + 2 < 128) {
            mbar_expect_tx(mbB + 8u * buf, 32768u);
            bulkcp(sb + SM_B + (uint)buf * 32768u,
                   (const char*)g_cbbf + (size_t)(codebase0 + (kt + 2) * 64) * 512,
                   32768u, mbB + 8u * buf);
        }
    }
}

// =====================================================================
// launch #5: exact fp32 rescore of candidates (one warp per row).
// Identical arithmetic order as always (lo/hi fma ascending d,
// g = fadd(lo,hi), s = fl(fl(zn+ce) - 2g)); float4 loads only change
// the load width, not rounding.
// =====================================================================
__global__ void k_rescore(const float* __restrict__ cb) {
    const int gw = (blockIdx.x * blockDim.x + threadIdx.x) >> 5;
    const int lane = threadIdx.x & 31;
    if (gw >= NROWS) return;
    const float4* zr4 = (const float4*)((const float*)g_zt4 + (size_t)gw * 256);
    const float zn = g_zn2[gw];
    const int cnt = g_ccnt[gw];
    float s = __int_as_float(0x7f800000);
    int bi = 0x7fffffff;
    if (cnt <= KCAND) {
        for (int ci = lane; ci < cnt; ci += 32) {
            int c = g_cand[gw * KCAND + ci];
            const float4* er4 = (const float4*)(cb + (size_t)c * 256);
            float lo = 0.f, hi = 0.f;
#pragma unroll 8
            for (int d4 = 0; d4 < 64; ++d4) {
                float4 zv = zr4[d4];
                float4 ev = __ldg(&er4[d4]);
                lo = __fmaf_rn(zv.x, ev.x, lo);
                hi = __fmaf_rn(zv.y, ev.y, hi);
                lo = __fmaf_rn(zv.z, ev.z, lo);
                hi = __fmaf_rn(zv.w, ev.w, hi);
            }
            float g = __fadd_rn(lo, hi);
            float sc = __fmaf_rn(-2.0f, g, __fadd_rn(zn, g_ce[c]));
            if (sc < s || (sc == s && c < bi)) { s = sc; bi = c; }
        }
    } else {
        // overflow fallback: exact full-row scan
        for (int c = lane; c < KCODES; c += 32) {
            const float4* er4 = (const float4*)(cb + (size_t)c * 256);
            float lo = 0.f, hi = 0.f;
            for (int d4 = 0; d4 < 64; ++d4) {
                float4 zv = zr4[d4];
                float4 ev = __ldg(&er4[d4]);
                lo = __fmaf_rn(zv.x, ev.x, lo);
                hi = __fmaf_rn(zv.y, ev.y, hi);
                lo = __fmaf_rn(zv.z, ev.z, lo);
                hi = __fmaf_rn(zv.w, ev.w, hi);
            }
            float g = __fadd_rn(lo, hi);
            float sc = __fmaf_rn(-2.0f, g, __fadd_rn(zn, g_ce[c]));
            if (sc < s || (sc == s && c < bi)) { s = sc; bi = c; }
        }
    }
#pragma unroll
    for (int o = 16; o; o >>= 1) {
        float s2 = __shfl_xor_sync(0xffffffffu, s, o);
        int b2 = __shfl_xor_sync(0xffffffffu, bi, o);
        if (s2 < s || (s2 == s && b2 < bi)) { s = s2; bi = b2; }
    }
    if (lane == 0) g_idx[gw] = bi;
}

// =====================================================================
// launch #6: gather z_q = codebook[idx] and append idx (as float) if room
// =====================================================================
__global__ void k_gather(const float4* __restrict__ cb4, float* __restrict__ out,
                         int write_idx) {
    int t = blockIdx.x * 256 + threadIdx.x;
    int n = t >> 6, c4 = t & 63;
    int id = g_idx[n];
    ((float4*)out)[(size_t)n * 64 + c4] = cb4[(size_t)id * 64 + c4];
    if (write_idx && c4 == 0) out[NZQ + n] = (float)id;
}

// =====================================================================
extern "C" void kernel_launch(void* const* d_in, const int* in_sizes, int n_in,
                              void* d_out, int out_size) {
    const float* z  = (const float*)d_in[0];
    const float* cb = (const float*)d_in[1];

    k_transpose<<<dim3(32, 8, 16), dim3(32, 8)>>>(z);
    k_prep_norm<<<1024, 256>>>(cb);
    k_prep_bf16<<<4096, 256>>>((const float4*)cb);

    cudaFuncSetAttribute(k_mma_argmin, cudaFuncAttributeMaxDynamicSharedMemorySize,
                         SMEM_BYTES);
    k_mma_argmin<<<128, 1024, SMEM_BYTES>>>();

    k_rescore<<<2048, 256>>>(cb);

    int write_idx = (out_size >= NZQ + NROWS) ? 1 : 0;
    k_gather<<<4096, 256>>>((const float4*)cb, (float*)d_out, write_idx);
}

// round 14
// speedup vs baseline: 1.1755x; 1.1755x over previous
#include <cuda_runtime.h>
#include <cuda_bf16.h>
#include <cstdint>

// VectorQuantizer: z[16,256,32,32] fp32, codebook[16384,256] fp32
// out: z_q [16,32,32,256] flattened (4,194,304 floats) then idx (16384) as float.

#define NROWS 16384
#define KCODES 16384
#define NZQ (16384*256)
#define KCAND 64
#define WINDOW 2.0e-4f

typedef unsigned int uint;

// ---- scratch (device globals; no allocation allowed) ----
__device__ float4        g_zt4[NROWS * 64];      // z transposed [N][256] fp32, 16 MB
__device__ float         g_zn2[NROWS];
__device__ float         g_ce[KCODES];
__device__ int           g_idx[NROWS];
__device__ __nv_bfloat16 g_zbf[NROWS * 256];     // bf16, ldmatrix-swizzle baked, 8 MB
__device__ __nv_bfloat16 g_cbbf[KCODES * 256];   // bf16, ldmatrix-swizzle baked, 8 MB
__device__ int           g_cand[NROWS * KCAND];  // 4 MB
__device__ int           g_ccnt[NROWS];

// =====================================================================
// helpers (baseline sm_90 PTX only: compiles under compute_103 virtual)
// =====================================================================
__device__ __forceinline__ uint smem_u32(const void* p) {
    uint a;
    asm("{ .reg .u64 t; cvta.to.shared.u64 t, %1; cvt.u32.u64 %0, t; }"
        : "=r"(a) : "l"(p));
    return a;
}
__device__ __forceinline__ void mbar_init(uint addr, uint cnt) {
    asm volatile("mbarrier.init.shared.b64 [%0], %1;" :: "r"(addr), "r"(cnt) : "memory");
}
__device__ __forceinline__ void mbar_arrive(uint addr) {
    asm volatile("mbarrier.arrive.shared.b64 _, [%0];" :: "r"(addr) : "memory");
}
__device__ __forceinline__ void mbar_expect_tx(uint addr, uint tx) {
    asm volatile("mbarrier.arrive.expect_tx.shared.b64 _, [%0], %1;"
                 :: "r"(addr), "r"(tx) : "memory");
}
__device__ __forceinline__ void mbar_wait(uint addr, uint parity) {
    asm volatile("{\n\t.reg .pred P;\n\t"
                 "WL_%=:\n\t"
                 "mbarrier.try_wait.parity.acquire.cta.shared::cta.b64 P, [%0], %1, 0x989680;\n\t"
                 "@P bra WD_%=;\n\t"
                 "bra WL_%=;\n\t"
                 "WD_%=:\n\t}"
                 :: "r"(addr), "r"(parity) : "memory");
}
// 1D bulk copy gmem->smem, completion via mbarrier complete_tx
__device__ __forceinline__ void bulkcp(uint dst, const void* src, uint bytes,
                                       uint mbar) {
    asm volatile(
        "cp.async.bulk.shared::cluster.global.mbarrier::complete_tx::bytes "
        "[%0], [%1], %2, [%3];"
        :: "r"(dst), "l"(src), "r"(bytes), "r"(mbar) : "memory");
}
__device__ __forceinline__ void ldsm4(uint& r0, uint& r1, uint& r2, uint& r3,
                                      uint addr) {
    asm volatile("ldmatrix.sync.aligned.m8n8.x4.shared.b16 {%0,%1,%2,%3}, [%4];"
                 : "=r"(r0), "=r"(r1), "=r"(r2), "=r"(r3) : "r"(addr));
}
__device__ __forceinline__ void mma16816(float* c, const uint* a, const uint* b) {
    asm volatile("mma.sync.aligned.m16n8k16.row.col.f32.bf16.bf16.f32 "
                 "{%0,%1,%2,%3}, {%4,%5,%6,%7}, {%8,%9}, {%0,%1,%2,%3};"
                 : "+f"(c[0]), "+f"(c[1]), "+f"(c[2]), "+f"(c[3])
                 : "r"(a[0]), "r"(a[1]), "r"(a[2]), "r"(a[3]),
                   "r"(b[0]), "r"(b[1]));
}

// =====================================================================
// launch #1: transpose z [B=16, C=256, HW=1024] -> zt [n = b*1024+hw][c]
// =====================================================================
__global__ void k_transpose(const float* __restrict__ z) {
    __shared__ float t[32][33];
    int b = blockIdx.z, c0 = blockIdx.y * 32, hw0 = blockIdx.x * 32;
    float* zt = (float*)g_zt4;
#pragma unroll
    for (int r = 0; r < 4; r++) {
        int c = c0 + threadIdx.y + 8 * r;
        t[threadIdx.y + 8 * r][threadIdx.x] =
            z[((size_t)(b * 256 + c)) * 1024 + hw0 + threadIdx.x];
    }
    __syncthreads();
#pragma unroll
    for (int r = 0; r < 4; r++) {
        int hw = hw0 + threadIdx.y + 8 * r;
        zt[((size_t)(b * 1024 + hw)) * 256 + c0 + threadIdx.x] =
            t[threadIdx.x][threadIdx.y + 8 * r];
    }
}

// =====================================================================
// launch #2: both row-norm sets. rounded multiply + strictly sequential
// fp32 adds (XLA reduce semantics). blocks [0,512): z ; [512,1024): cb
// =====================================================================
__global__ void k_prep_norm(const float* __restrict__ cb) {
    __shared__ float s[32 * 257];
    const int zpart = blockIdx.x < 512;
    const int base = (zpart ? blockIdx.x : blockIdx.x - 512) * 32;
    const float* src = zpart ? (const float*)g_zt4 : cb;
    float* dst = zpart ? g_zn2 : g_ce;
    for (int off = threadIdx.x; off < 32 * 256; off += 256) {
        int r = off >> 8, d = off & 255;
        s[r * 257 + d] = src[(size_t)base * 256 + off];
    }
    __syncthreads();
    if (threadIdx.x < 32) {
        const float* row = &s[threadIdx.x * 257];
        float a = 0.f;
        for (int d = 0; d < 256; ++d) {
            float v = row[d];
            a = __fadd_rn(a, __fmul_rn(v, v));
        }
        dst[base + threadIdx.x] = a;
    }
}

// =====================================================================
// launch #3: fp32 -> bf16 with the ldmatrix XOR swizzle BAKED into gmem:
// 16B chunk ci of row c lands at byte  c*512 + ((ci ^ (c&7)) << 4).
// blocks [0,2048): z ; [2048,4096): codebook (+ zero cand counters)
// =====================================================================
__device__ __forceinline__ uint packbf(float x, float y) {
    __nv_bfloat162 h = __floats2bfloat162_rn(x, y);
    return *reinterpret_cast<uint*>(&h);
}
__global__ void k_prep_bf16(const float4* __restrict__ cb) {
    const int zpart = blockIdx.x < 2048;
    int t = (zpart ? blockIdx.x : blockIdx.x - 2048) * 256 + threadIdx.x;
    const float4* src = zpart ? g_zt4 : cb;
    float4 a = src[2 * t], b = src[2 * t + 1];
    uint4 o;
    o.x = packbf(a.x, a.y); o.y = packbf(a.z, a.w);
    o.z = packbf(b.x, b.y); o.w = packbf(b.z, b.w);
    int c = t >> 5, ci = t & 31;
    size_t addr = (size_t)c * 512 + (uint)((ci ^ (c & 7)) << 4);
    *(uint4*)((char*)(zpart ? g_zbf : g_cbbf) + addr) = o;
    if (!zpart && blockIdx.x < 2048 + 64)
        g_ccnt[(blockIdx.x - 2048) * 256 + threadIdx.x] = 0;  // re-zeroed per replay
}

// =====================================================================
// launch #4: bf16 mma.sync GEMM + approx argmin + candidate collection.
//
// grid 128 = 64 M-blocks x 2 N-halves. 512 threads, 16 warps.
// Warp tile = 16 rows x 64 codes (full B width): warpM = wid.
// A fragments for ALL 16 k-steps are loaded into registers ONCE
// (64 regs) -> zero A-ldsm / A-address work in the mainloop.
// B ring: 3 x 32 KB buffers, mbarrier pairs full[b] (tx) / consumed[b]
// (16 warp arrives). NO __syncthreads in the mainloop -> warps drift
// across tiles instead of convoying at a per-tile barrier.
// Row ownership: each row belongs to exactly one warp (4 lanes), so the
// running row-min lives in registers + 2 shfl_xor, no smem, no atomics.
// Candidate append: s < rowmin_prev + WINDOW; the true argmin always
// satisfies s* <= rowmin_prev, so it is always captured; append ORDER
// may vary across replays but the rescore (min + lowest-index
// tie-break over the set, exact full-scan on overflow) is
// order-invariant -> output deterministic.
// =====================================================================
#define SM_A   0u
#define SM_B   131072u
#define SM_BAR 229376u
#define SMEM_BYTES 229440

__global__ __launch_bounds__(512, 1) void k_mma_argmin() {
    extern __shared__ char smem[];
    const uint sb = smem_u32(smem);
    const int tid = threadIdx.x, lane = tid & 31, wid = tid >> 5;
    const int mblk = blockIdx.x >> 1, nhalf = blockIdx.x & 1;
    const int rowbase = mblk * 256, codebase0 = nhalf * 8192;

    const uint mbA   = sb + SM_BAR;        // A full
    const uint mbF   = sb + SM_BAR + 8;    // full[3]    at +8,+16,+24
    const uint mbC   = sb + SM_BAR + 32;   // consumed[3] at +32,+40,+48

    if (tid == 0) {
        mbar_init(mbA, 1);
#pragma unroll
        for (int b = 0; b < 3; b++) {
            mbar_init(mbF + 8u * b, 1);
            mbar_init(mbC + 8u * b, 16);
        }
    }
    __syncthreads();   // mbar init visible before any wait/bulk
    if (tid == 0) {
        mbar_expect_tx(mbA, 131072u);
        bulkcp(sb + SM_A, (const char*)g_zbf + (size_t)rowbase * 512, 131072u, mbA);
#pragma unroll
        for (int b = 0; b < 3; b++) {
            mbar_expect_tx(mbF + 8u * b, 32768u);
            bulkcp(sb + SM_B + 32768u * b,
                   (const char*)g_cbbf + (size_t)(codebase0 + 64 * b) * 512,
                   32768u, mbF + 8u * b);
        }
    }

    // ---- per-thread geometry ----
    const int rowA = (lane & 7) + ((lane >> 3) & 1) * 8;
    const int aK = lane >> 4;
    const int rA = wid * 16 + rowA;
    const uint aAddr = sb + SM_A + (uint)rA * 512u;
    const int aSw = rA & 7;

    const int rowB = (lane & 7) + (lane >> 4) * 8;     // 0..15
    const int bK = (lane >> 3) & 1;
    const int bSw = rowB & 7;                          // same for all 4 bases

    float zn2r[2];
#pragma unroll
    for (int h = 0; h < 2; h++)
        zn2r[h] = g_zn2[rowbase + wid * 16 + (lane >> 2) + 8 * h];
    const int colq = (lane & 3) * 2;

    // ---- load ALL A fragments into registers (once) ----
    mbar_wait(mbA, 0);
    uint aF[16][4];
#pragma unroll
    for (int ks = 0; ks < 16; ++ks)
        ldsm4(aF[ks][0], aF[ks][1], aF[ks][2], aF[ks][3],
              aAddr + (uint)(((2 * ks + aK) ^ aSw) << 4));

    float minv[2] = { __int_as_float(0x7f800000), __int_as_float(0x7f800000) };

    for (int kt = 0; kt < 128; ++kt) {
        const int buf = kt - (kt / 3) * 3;       // kt % 3
        const uint par = (uint)(kt / 3) & 1u;
        mbar_wait(mbF + 8u * buf, par);

        float acc[8][4];
#pragma unroll
        for (int nf = 0; nf < 8; nf++)
#pragma unroll
            for (int v = 0; v < 4; v++) acc[nf][v] = 0.f;

        const uint bb = sb + SM_B + 32768u * buf + (uint)rowB * 512u;
#pragma unroll
        for (int ks = 0; ks < 16; ++ks) {
            const uint ch = (uint)(((2 * ks + bK) ^ bSw) << 4);
            uint b0[4], b1[4], b2[4], b3[4];
            ldsm4(b0[0], b0[1], b0[2], b0[3], bb + ch);
            ldsm4(b1[0], b1[1], b1[2], b1[3], bb + 16u * 512u + ch);
            ldsm4(b2[0], b2[1], b2[2], b2[3], bb + 32u * 512u + ch);
            ldsm4(b3[0], b3[1], b3[2], b3[3], bb + 48u * 512u + ch);
            mma16816(acc[0], aF[ks], b0);
            mma16816(acc[1], aF[ks], b0 + 2);
            mma16816(acc[2], aF[ks], b1);
            mma16816(acc[3], aF[ks], b1 + 2);
            mma16816(acc[4], aF[ks], b2);
            mma16816(acc[5], aF[ks], b2 + 2);
            mma16816(acc[6], aF[ks], b3);
            mma16816(acc[7], aF[ks], b3 + 2);
        }

        // ---- epilogue: scores, row-min via shfl, window appends ----
        const int ctile = codebase0 + kt * 64;
        float ce_r[16];
#pragma unroll
        for (int nf = 0; nf < 8; nf++)
#pragma unroll
            for (int q = 0; q < 2; q++)
                ce_r[nf * 2 + q] = __ldg(&g_ce[ctile + nf * 8 + colq + q]);

#pragma unroll
        for (int h = 0; h < 2; h++) {
            const float zn = zn2r[h];
            float tmin = __int_as_float(0x7f800000);
#pragma unroll
            for (int nf = 0; nf < 8; nf++)
#pragma unroll
                for (int q = 0; q < 2; q++) {
                    float s = __fmaf_rn(-2.f, acc[nf][h * 2 + q],
                                        __fadd_rn(zn, ce_r[nf * 2 + q]));
                    acc[nf][h * 2 + q] = s;
                    tmin = fminf(tmin, s);
                }
            // 4-lane row-group reduction (lanes differing in bits 0,1)
            tmin = fminf(tmin, __shfl_xor_sync(0xffffffffu, tmin, 1));
            tmin = fminf(tmin, __shfl_xor_sync(0xffffffffu, tmin, 2));
            const float mwin = (kt == 0 ? tmin : minv[h]) + WINDOW;
            const int grow = rowbase + wid * 16 + (lane >> 2) + 8 * h;
#pragma unroll
            for (int nf = 0; nf < 8; nf++)
#pragma unroll
                for (int q = 0; q < 2; q++) {
                    if (acc[nf][h * 2 + q] < mwin) {
                        int pos = atomicAdd(&g_ccnt[grow], 1);
                        if (pos < KCAND)
                            g_cand[grow * KCAND + pos] = ctile + nf * 8 + colq + q;
                    }
                }
            minv[h] = fminf(minv[h], tmin);
        }

        // ---- ring bookkeeping (no CTA barrier) ----
        if (lane == 0) mbar_arrive(mbC + 8u * buf);
        if (tid == 0 && kt + 3 < 128) {
            mbar_wait(mbC + 8u * buf, par);    // all 16 warps done with tile kt
            mbar_expect_tx(mbF + 8u * buf, 32768u);
            bulkcp(sb + SM_B + 32768u * buf,
                   (const char*)g_cbbf + (size_t)(codebase0 + (kt + 3) * 64) * 512,
                   32768u, mbF + 8u * buf);
        }
    }
}

// =====================================================================
// launch #5: exact fp32 rescore of candidates (one warp per row).
// lo/hi fma ascending d, g = fadd(lo,hi), s = fl(fl(zn+ce) - 2g)
// =====================================================================
__global__ void k_rescore(const float* __restrict__ cb) {
    const int gw = (blockIdx.x * blockDim.x + threadIdx.x) >> 5;
    const int lane = threadIdx.x & 31;
    if (gw >= NROWS) return;
    const float4* zr4 = (const float4*)((const float*)g_zt4 + (size_t)gw * 256);
    const float zn = g_zn2[gw];
    const int cnt = g_ccnt[gw];
    float s = __int_as_float(0x7f800000);
    int bi = 0x7fffffff;
    if (cnt <= KCAND) {
        for (int ci = lane; ci < cnt; ci += 32) {
            int c = g_cand[gw * KCAND + ci];
            const float4* er4 = (const float4*)(cb + (size_t)c * 256);
            float lo = 0.f, hi = 0.f;
#pragma unroll 8
            for (int d4 = 0; d4 < 64; ++d4) {
                float4 zv = zr4[d4];
                float4 ev = __ldg(&er4[d4]);
                lo = __fmaf_rn(zv.x, ev.x, lo);
                hi = __fmaf_rn(zv.y, ev.y, hi);
                lo = __fmaf_rn(zv.z, ev.z, lo);
                hi = __fmaf_rn(zv.w, ev.w, hi);
            }
            float g = __fadd_rn(lo, hi);
            float sc = __fmaf_rn(-2.0f, g, __fadd_rn(zn, g_ce[c]));
            if (sc < s || (sc == s && c < bi)) { s = sc; bi = c; }
        }
    } else {
        // overflow fallback: exact full-row scan
        for (int c = lane; c < KCODES; c += 32) {
            const float4* er4 = (const float4*)(cb + (size_t)c * 256);
            float lo = 0.f, hi = 0.f;
            for (int d4 = 0; d4 < 64; ++d4) {
                float4 zv = zr4[d4];
                float4 ev = __ldg(&er4[d4]);
                lo = __fmaf_rn(zv.x, ev.x, lo);
                hi = __fmaf_rn(zv.y, ev.y, hi);
                lo = __fmaf_rn(zv.z, ev.z, lo);
                hi = __fmaf_rn(zv.w, ev.w, hi);
            }
            float g = __fadd_rn(lo, hi);
            float sc = __fmaf_rn(-2.0f, g, __fadd_rn(zn, g_ce[c]));
            if (sc < s || (sc == s && c < bi)) { s = sc; bi = c; }
        }
    }
#pragma unroll
    for (int o = 16; o; o >>= 1) {
        float s2 = __shfl_xor_sync(0xffffffffu, s, o);
        int b2 = __shfl_xor_sync(0xffffffffu, bi, o);
        if (s2 < s || (s2 == s && b2 < bi)) { s = s2; bi = b2; }
    }
    if (lane == 0) g_idx[gw] = bi;
}

// =====================================================================
// launch #6: gather z_q = codebook[idx] and append idx (as float) if room
// =====================================================================
__global__ void k_gather(const float4* __restrict__ cb4, float* __restrict__ out,
                         int write_idx) {
    int t = blockIdx.x * 256 + threadIdx.x;
    int n = t >> 6, c4 = t & 63;
    int id = g_idx[n];
    ((float4*)out)[(size_t)n * 64 + c4] = cb4[(size_t)id * 64 + c4];
    if (write_idx && c4 == 0) out[NZQ + n] = (float)id;
}

// =====================================================================
extern "C" void kernel_launch(void* const* d_in, const int* in_sizes, int n_in,
                              void* d_out, int out_size) {
    const float* z  = (const float*)d_in[0];
    const float* cb = (const float*)d_in[1];

    k_transpose<<<dim3(32, 8, 16), dim3(32, 8)>>>(z);
    k_prep_norm<<<1024, 256>>>(cb);
    k_prep_bf16<<<4096, 256>>>((const float4*)cb);

    cudaFuncSetAttribute(k_mma_argmin, cudaFuncAttributeMaxDynamicSharedMemorySize,
                         SMEM_BYTES);
    k_mma_argmin<<<128, 512, SMEM_BYTES>>>();

    k_rescore<<<2048, 256>>>(cb);

    int write_idx = (out_size >= NZQ + NROWS) ? 1 : 0;
    k_gather<<<4096, 256>>>((const float4*)cb, (float*)d_out, write_idx);
}

// round 15
// speedup vs baseline: 1.3660x; 1.1621x over previous
#include <cuda_runtime.h>
#include <cuda_bf16.h>
#include <cstdint>

// VectorQuantizer: z[16,256,32,32] fp32, codebook[16384,256] fp32
// out: z_q [16,32,32,256] flattened (4,194,304 floats) then idx (16384) as float.

#define NROWS 16384
#define KCODES 16384
#define NZQ (16384*256)
#define KCAND 64
#define WINDOW 2.0e-4f

typedef unsigned int uint;

// ---- scratch (device globals; no allocation allowed) ----
__device__ float4        g_zt4[NROWS * 64];      // z transposed [N][256] fp32, 16 MB
__device__ float         g_zn2[NROWS];
__device__ float         g_ce[KCODES];
__device__ int           g_idx[NROWS];
__device__ __nv_bfloat16 g_zbf[NROWS * 256];     // bf16, ldmatrix-swizzle baked, 8 MB
__device__ __nv_bfloat16 g_cbbf[KCODES * 256];   // bf16, ldmatrix-swizzle baked, 8 MB
__device__ int           g_cand[NROWS * KCAND];  // 4 MB
__device__ int           g_ccnt[NROWS];

// =====================================================================
// helpers (baseline sm_90 PTX only: compiles under compute_103 virtual)
// =====================================================================
__device__ __forceinline__ uint smem_u32(const void* p) {
    uint a;
    asm("{ .reg .u64 t; cvta.to.shared.u64 t, %1; cvt.u32.u64 %0, t; }"
        : "=r"(a) : "l"(p));
    return a;
}
__device__ __forceinline__ void mbar_init(uint addr, uint cnt) {
    asm volatile("mbarrier.init.shared.b64 [%0], %1;" :: "r"(addr), "r"(cnt) : "memory");
}
__device__ __forceinline__ void mbar_arrive(uint addr) {
    asm volatile("mbarrier.arrive.shared.b64 _, [%0];" :: "r"(addr) : "memory");
}
__device__ __forceinline__ void mbar_expect_tx(uint addr, uint tx) {
    asm volatile("mbarrier.arrive.expect_tx.shared.b64 _, [%0], %1;"
                 :: "r"(addr), "r"(tx) : "memory");
}
__device__ __forceinline__ void mbar_wait(uint addr, uint parity) {
    asm volatile("{\n\t.reg .pred P;\n\t"
                 "WL_%=:\n\t"
                 "mbarrier.try_wait.parity.acquire.cta.shared::cta.b64 P, [%0], %1, 0x989680;\n\t"
                 "@P bra WD_%=;\n\t"
                 "bra WL_%=;\n\t"
                 "WD_%=:\n\t}"
                 :: "r"(addr), "r"(parity) : "memory");
}
// 1D bulk copy gmem->smem, completion via mbarrier complete_tx
__device__ __forceinline__ void bulkcp(uint dst, const void* src, uint bytes,
                                       uint mbar) {
    asm volatile(
        "cp.async.bulk.shared::cluster.global.mbarrier::complete_tx::bytes "
        "[%0], [%1], %2, [%3];"
        :: "r"(dst), "l"(src), "r"(bytes), "r"(mbar) : "memory");
}
__device__ __forceinline__ void ldsm4(uint& r0, uint& r1, uint& r2, uint& r3,
                                      uint addr) {
    asm volatile("ldmatrix.sync.aligned.m8n8.x4.shared.b16 {%0,%1,%2,%3}, [%4];"
                 : "=r"(r0), "=r"(r1), "=r"(r2), "=r"(r3) : "r"(addr));
}
__device__ __forceinline__ void mma16816(float* c, const uint* a, const uint* b) {
    asm volatile("mma.sync.aligned.m16n8k16.row.col.f32.bf16.bf16.f32 "
                 "{%0,%1,%2,%3}, {%4,%5,%6,%7}, {%8,%9}, {%0,%1,%2,%3};"
                 : "+f"(c[0]), "+f"(c[1]), "+f"(c[2]), "+f"(c[3])
                 : "r"(a[0]), "r"(a[1]), "r"(a[2]), "r"(a[3]),
                   "r"(b[0]), "r"(b[1]));
}
__device__ __forceinline__ uint packbf(float x, float y) {
    __nv_bfloat162 h = __floats2bfloat162_rn(x, y);
    return *reinterpret_cast<uint*>(&h);
}

// =====================================================================
// launch #1: transpose z [B=16, C=256, HW=1024] -> zt [n][c]  AND emit
// g_zbf (bf16, ldmatrix-swizzle baked) directly from the smem tile.
// Swizzle: 16B chunk ci of row n lands at byte n*512 + ((ci ^ (n&7))<<4).
// =====================================================================
__global__ void k_transpose(const float* __restrict__ z) {
    __shared__ float t[32][33];
    int b = blockIdx.z, c0 = blockIdx.y * 32, hw0 = blockIdx.x * 32;
    float* zt = (float*)g_zt4;
#pragma unroll
    for (int r = 0; r < 4; r++) {
        int c = c0 + threadIdx.y + 8 * r;
        t[threadIdx.y + 8 * r][threadIdx.x] =
            z[((size_t)(b * 256 + c)) * 1024 + hw0 + threadIdx.x];
    }
    __syncthreads();
#pragma unroll
    for (int r = 0; r < 4; r++) {
        int hw = hw0 + threadIdx.y + 8 * r;
        zt[((size_t)(b * 1024 + hw)) * 256 + c0 + threadIdx.x] =
            t[threadIdx.x][threadIdx.y + 8 * r];
    }
    // fused bf16 + baked-swizzle emission (128 threads, 16B each)
    int flat = threadIdx.y * 32 + threadIdx.x;
    if (flat < 128) {
        int nl = flat >> 2, ch = flat & 3;
        int n = b * 1024 + hw0 + nl;
        uint4 o;
        o.x = packbf(t[ch * 8 + 0][nl], t[ch * 8 + 1][nl]);
        o.y = packbf(t[ch * 8 + 2][nl], t[ch * 8 + 3][nl]);
        o.z = packbf(t[ch * 8 + 4][nl], t[ch * 8 + 5][nl]);
        o.w = packbf(t[ch * 8 + 6][nl], t[ch * 8 + 7][nl]);
        int ci = (c0 >> 3) + ch;
        *(uint4*)((char*)g_zbf + (size_t)n * 512 + (uint)((ci ^ (n & 7)) << 4)) = o;
    }
}

// =====================================================================
// launch #2: fused prep.
// blocks [0,512): z row-norms (strictly sequential fp32 adds, XLA
// semantics); [512,1024): codebook row-norms; [1024,3072): codebook
// fp32->bf16 with baked swizzle (+ first 64 of those zero g_ccnt).
// =====================================================================
__global__ void k_prep2(const float* __restrict__ cb) {
    if (blockIdx.x < 1024) {
        __shared__ float s[32 * 257];
        const int zpart = blockIdx.x < 512;
        const int base = (zpart ? blockIdx.x : blockIdx.x - 512) * 32;
        const float* src = zpart ? (const float*)g_zt4 : cb;
        float* dst = zpart ? g_zn2 : g_ce;
        for (int off = threadIdx.x; off < 32 * 256; off += 256) {
            int r = off >> 8, d = off & 255;
            s[r * 257 + d] = src[(size_t)base * 256 + off];
        }
        __syncthreads();
        if (threadIdx.x < 32) {
            const float* row = &s[threadIdx.x * 257];
            float a = 0.f;
            for (int d = 0; d < 256; ++d) {
                float v = row[d];
                a = __fadd_rn(a, __fmul_rn(v, v));
            }
            dst[base + threadIdx.x] = a;
        }
    } else {
        int t = (blockIdx.x - 1024) * 256 + threadIdx.x;
        const float4* src = (const float4*)cb;
        float4 a = src[2 * t], b2 = src[2 * t + 1];
        uint4 o;
        o.x = packbf(a.x, a.y); o.y = packbf(a.z, a.w);
        o.z = packbf(b2.x, b2.y); o.w = packbf(b2.z, b2.w);
        int c = t >> 5, ci = t & 31;
        *(uint4*)((char*)g_cbbf + (size_t)c * 512 + (uint)((ci ^ (c & 7)) << 4)) = o;
        if (blockIdx.x < 1024 + 64)
            g_ccnt[(blockIdx.x - 1024) * 256 + threadIdx.x] = 0;  // per replay
    }
}

// =====================================================================
// launch #3: bf16 mma.sync GEMM + approx argmin + candidate collection.
//
// grid 128 = 64 M-blocks x 2 N-halves. 512 threads, 16 warps.
// Warp tile = 16 rows x 64 codes; A fragments for all 16 k-steps in
// registers (loaded once). B ring: 3 x 32 KB, mbarrier full/consumed,
// NO __syncthreads in the mainloop (warps drift across tiles).
// Approx score uses s' = ce - 2*g (zn dropped: row-constant shift
// cannot change the argmin or the window SET; only the exact rescore
// needs the reference expression). s' has ~1e-10 ulp so the window
// keeps only genuinely-close candidates (~2-5/row).
// Append guard: whole 16-way append loop skipped unless this tile's
// row-min is inside the window (rare) -> epilogue is min-tree + 2 shfl.
// The true argmin always lands inside the window (|ordering error| <=
// 7e-5 << 2e-4), so it is always captured; append order may vary but
// rescore (min + lowest-index tie-break, exact full scan on overflow)
// is order-invariant -> deterministic output.
// =====================================================================
#define SM_A   0u
#define SM_B   131072u
#define SM_BAR 229376u
#define SMEM_BYTES 229440

__global__ __launch_bounds__(512, 1) void k_mma_argmin() {
    extern __shared__ char smem[];
    const uint sb = smem_u32(smem);
    const int tid = threadIdx.x, lane = tid & 31, wid = tid >> 5;
    const int mblk = blockIdx.x >> 1, nhalf = blockIdx.x & 1;
    const int rowbase = mblk * 256, codebase0 = nhalf * 8192;

    const uint mbA = sb + SM_BAR;        // A full
    const uint mbF = sb + SM_BAR + 8;    // full[3]     at +8,+16,+24
    const uint mbC = sb + SM_BAR + 32;   // consumed[3] at +32,+40,+48

    if (tid == 0) {
        mbar_init(mbA, 1);
#pragma unroll
        for (int b = 0; b < 3; b++) {
            mbar_init(mbF + 8u * b, 1);
            mbar_init(mbC + 8u * b, 16);
        }
    }
    __syncthreads();   // mbar init visible before any wait/bulk
    if (tid == 0) {
        mbar_expect_tx(mbA, 131072u);
        bulkcp(sb + SM_A, (const char*)g_zbf + (size_t)rowbase * 512, 131072u, mbA);
#pragma unroll
        for (int b = 0; b < 3; b++) {
            mbar_expect_tx(mbF + 8u * b, 32768u);
            bulkcp(sb + SM_B + 32768u * b,
                   (const char*)g_cbbf + (size_t)(codebase0 + 64 * b) * 512,
                   32768u, mbF + 8u * b);
        }
    }

    // ---- per-thread geometry ----
    const int rowA = (lane & 7) + ((lane >> 3) & 1) * 8;
    const int aK = lane >> 4;
    const int rA = wid * 16 + rowA;
    const uint aAddr = sb + SM_A + (uint)rA * 512u;
    const int aSw = rA & 7;

    const int rowB = (lane & 7) + (lane >> 4) * 8;     // 0..15
    const int bK = (lane >> 3) & 1;
    const int bSw = rowB & 7;

    const int colq = (lane & 3) * 2;

    // ---- load ALL A fragments into registers (once) ----
    mbar_wait(mbA, 0);
    uint aF[16][4];
#pragma unroll
    for (int ks = 0; ks < 16; ++ks)
        ldsm4(aF[ks][0], aF[ks][1], aF[ks][2], aF[ks][3],
              aAddr + (uint)(((2 * ks + aK) ^ aSw) << 4));

    float minv[2] = { __int_as_float(0x7f800000), __int_as_float(0x7f800000) };

    for (int kt = 0; kt < 128; ++kt) {
        const int buf = kt - (kt / 3) * 3;       // kt % 3
        const uint par = (uint)(kt / 3) & 1u;
        mbar_wait(mbF + 8u * buf, par);

        float acc[8][4];
#pragma unroll
        for (int nf = 0; nf < 8; nf++)
#pragma unroll
            for (int v = 0; v < 4; v++) acc[nf][v] = 0.f;

        const uint bb = sb + SM_B + 32768u * buf + (uint)rowB * 512u;
#pragma unroll
        for (int ks = 0; ks < 16; ++ks) {
            const uint ch = (uint)(((2 * ks + bK) ^ bSw) << 4);
            uint b0[4], b1[4], b2[4], b3[4];
            ldsm4(b0[0], b0[1], b0[2], b0[3], bb + ch);
            ldsm4(b1[0], b1[1], b1[2], b1[3], bb + 16u * 512u + ch);
            ldsm4(b2[0], b2[1], b2[2], b2[3], bb + 32u * 512u + ch);
            ldsm4(b3[0], b3[1], b3[2], b3[3], bb + 48u * 512u + ch);
            mma16816(acc[0], aF[ks], b0);
            mma16816(acc[1], aF[ks], b0 + 2);
            mma16816(acc[2], aF[ks], b1);
            mma16816(acc[3], aF[ks], b1 + 2);
            mma16816(acc[4], aF[ks], b2);
            mma16816(acc[5], aF[ks], b2 + 2);
            mma16816(acc[6], aF[ks], b3);
            mma16816(acc[7], aF[ks], b3 + 2);
        }

        // ---- epilogue: s' = ce - 2g, row-min via shfl, rare appends ----
        const int ctile = codebase0 + kt * 64;
        float ce_r[16];
#pragma unroll
        for (int nf = 0; nf < 8; nf++) {
            float2 cc = __ldg((const float2*)&g_ce[ctile + nf * 8 + colq]);
            ce_r[nf * 2 + 0] = cc.x;
            ce_r[nf * 2 + 1] = cc.y;
        }

#pragma unroll
        for (int h = 0; h < 2; h++) {
            float tmin = __int_as_float(0x7f800000);
#pragma unroll
            for (int nf = 0; nf < 8; nf++)
#pragma unroll
                for (int q = 0; q < 2; q++) {
                    float s = __fmaf_rn(-2.f, acc[nf][h * 2 + q],
                                        ce_r[nf * 2 + q]);
                    acc[nf][h * 2 + q] = s;
                    tmin = fminf(tmin, s);
                }
            // 4-lane row-group reduction (lanes differing in bits 0,1)
            tmin = fminf(tmin, __shfl_xor_sync(0xffffffffu, tmin, 1));
            tmin = fminf(tmin, __shfl_xor_sync(0xffffffffu, tmin, 2));
            const float mwin = (kt == 0 ? tmin : minv[h]) + WINDOW;
            if (tmin < mwin) {            // rare: this tile touches the window
                const int grow = rowbase + wid * 16 + (lane >> 2) + 8 * h;
#pragma unroll
                for (int nf = 0; nf < 8; nf++)
#pragma unroll
                    for (int q = 0; q < 2; q++) {
                        if (acc[nf][h * 2 + q] < mwin) {
                            int pos = atomicAdd(&g_ccnt[grow], 1);
                            if (pos < KCAND)
                                g_cand[grow * KCAND + pos] =
                                    ctile + nf * 8 + colq + q;
                        }
                    }
            }
            minv[h] = fminf(minv[h], tmin);
        }

        // ---- ring bookkeeping (no CTA barrier) ----
        if (lane == 0) mbar_arrive(mbC + 8u * buf);
        if (tid == 0 && kt + 3 < 128) {
            mbar_wait(mbC + 8u * buf, par);    // all 16 warps done with tile kt
            mbar_expect_tx(mbF + 8u * buf, 32768u);
            bulkcp(sb + SM_B + 32768u * buf,
                   (const char*)g_cbbf + (size_t)(codebase0 + (kt + 3) * 64) * 512,
                   32768u, mbF + 8u * buf);
        }
    }
}

// =====================================================================
// launch #4: exact fp32 rescore of candidates (one warp per row).
// lo/hi fma ascending d, g = fadd(lo,hi), s = fl(fl(zn+ce) - 2g)
// (the reference-matched expression; unchanged since R5).
// =====================================================================
__global__ void k_rescore(const float* __restrict__ cb) {
    const int gw = (blockIdx.x * blockDim.x + threadIdx.x) >> 5;
    const int lane = threadIdx.x & 31;
    if (gw >= NROWS) return;
    const float4* zr4 = (const float4*)((const float*)g_zt4 + (size_t)gw * 256);
    const float zn = g_zn2[gw];
    const int cnt = g_ccnt[gw];
    float s = __int_as_float(0x7f800000);
    int bi = 0x7fffffff;
    if (cnt <= KCAND) {
        for (int ci = lane; ci < cnt; ci += 32) {
            int c = g_cand[gw * KCAND + ci];
            const float4* er4 = (const float4*)(cb + (size_t)c * 256);
            float lo = 0.f, hi = 0.f;
#pragma unroll 8
            for (int d4 = 0; d4 < 64; ++d4) {
                float4 zv = zr4[d4];
                float4 ev = __ldg(&er4[d4]);
                lo = __fmaf_rn(zv.x, ev.x, lo);
                hi = __fmaf_rn(zv.y, ev.y, hi);
                lo = __fmaf_rn(zv.z, ev.z, lo);
                hi = __fmaf_rn(zv.w, ev.w, hi);
            }
            float g = __fadd_rn(lo, hi);
            float sc = __fmaf_rn(-2.0f, g, __fadd_rn(zn, g_ce[c]));
            if (sc < s || (sc == s && c < bi)) { s = sc; bi = c; }
        }
    } else {
        // overflow fallback: exact full-row scan
        for (int c = lane; c < KCODES; c += 32) {
            const float4* er4 = (const float4*)(cb + (size_t)c * 256);
            float lo = 0.f, hi = 0.f;
            for (int d4 = 0; d4 < 64; ++d4) {
                float4 zv = zr4[d4];
                float4 ev = __ldg(&er4[d4]);
                lo = __fmaf_rn(zv.x, ev.x, lo);
                hi = __fmaf_rn(zv.y, ev.y, hi);
                lo = __fmaf_rn(zv.z, ev.z, lo);
                hi = __fmaf_rn(zv.w, ev.w, hi);
            }
            float g = __fadd_rn(lo, hi);
            float sc = __fmaf_rn(-2.0f, g, __fadd_rn(zn, g_ce[c]));
            if (sc < s || (sc == s && c < bi)) { s = sc; bi = c; }
        }
    }
#pragma unroll
    for (int o = 16; o; o >>= 1) {
        float s2 = __shfl_xor_sync(0xffffffffu, s, o);
        int b2 = __shfl_xor_sync(0xffffffffu, bi, o);
        if (s2 < s || (s2 == s && b2 < bi)) { s = s2; bi = b2; }
    }
    if (lane == 0) g_idx[gw] = bi;
}

// =====================================================================
// launch #5: gather z_q = codebook[idx] and append idx (as float) if room
// =====================================================================
__global__ void k_gather(const float4* __restrict__ cb4, float* __restrict__ out,
                         int write_idx) {
    int t = blockIdx.x * 256 + threadIdx.x;
    int n = t >> 6, c4 = t & 63;
    int id = g_idx[n];
    ((float4*)out)[(size_t)n * 64 + c4] = cb4[(size_t)id * 64 + c4];
    if (write_idx && c4 == 0) out[NZQ + n] = (float)id;
}

// =====================================================================
extern "C" void kernel_launch(void* const* d_in, const int* in_sizes, int n_in,
                              void* d_out, int out_size) {
    const float* z  = (const float*)d_in[0];
    const float* cb = (const float*)d_in[1];

    k_transpose<<<dim3(32, 8, 16), dim3(32, 8)>>>(z);
    k_prep2<<<3072, 256>>>(cb);

    cudaFuncSetAttribute(k_mma_argmin, cudaFuncAttributeMaxDynamicSharedMemorySize,
                         SMEM_BYTES);
    k_mma_argmin<<<128, 512, SMEM_BYTES>>>();

    k_rescore<<<2048, 256>>>(cb);

    int write_idx = (out_size >= NZQ + NROWS) ? 1 : 0;
    k_gather<<<4096, 256>>>((const float4*)cb, (float*)d_out, write_idx);
}

// round 16
// speedup vs baseline: 1.4149x; 1.0357x over previous
#include <cuda_runtime.h>
#include <cuda_bf16.h>
#include <cstdint>

// VectorQuantizer: z[16,256,32,32] fp32, codebook[16384,256] fp32
// out: z_q [16,32,32,256] flattened (4,194,304 floats) then idx (16384) as float.

#define NROWS 16384
#define KCODES 16384
#define NZQ (16384*256)
#define KCAND 64
#define WINDOW 2.0e-4f

typedef unsigned int uint;

// ---- scratch (device globals; no allocation allowed) ----
__device__ float4        g_zt4[NROWS * 64];      // z transposed [N][256] fp32, 16 MB
__device__ float         g_zn2[NROWS];
__device__ float         g_ce[KCODES];
__device__ __nv_bfloat16 g_zbf[NROWS * 256];     // bf16, ldmatrix-swizzle baked, 8 MB
__device__ __nv_bfloat16 g_cbbf[KCODES * 256];   // bf16, ldmatrix-swizzle baked, 8 MB
__device__ int           g_cand[NROWS * KCAND];  // 4 MB
__device__ int           g_ccnt[NROWS];

// =====================================================================
// helpers (baseline sm_90 PTX only: compiles under compute_103 virtual)
// =====================================================================
__device__ __forceinline__ uint smem_u32(const void* p) {
    uint a;
    asm("{ .reg .u64 t; cvta.to.shared.u64 t, %1; cvt.u32.u64 %0, t; }"
        : "=r"(a) : "l"(p));
    return a;
}
__device__ __forceinline__ void mbar_init(uint addr, uint cnt) {
    asm volatile("mbarrier.init.shared.b64 [%0], %1;" :: "r"(addr), "r"(cnt) : "memory");
}
__device__ __forceinline__ void mbar_arrive(uint addr) {
    asm volatile("mbarrier.arrive.shared.b64 _, [%0];" :: "r"(addr) : "memory");
}
__device__ __forceinline__ void mbar_expect_tx(uint addr, uint tx) {
    asm volatile("mbarrier.arrive.expect_tx.shared.b64 _, [%0], %1;"
                 :: "r"(addr), "r"(tx) : "memory");
}
__device__ __forceinline__ void mbar_wait(uint addr, uint parity) {
    asm volatile("{\n\t.reg .pred P;\n\t"
                 "WL_%=:\n\t"
                 "mbarrier.try_wait.parity.acquire.cta.shared::cta.b64 P, [%0], %1, 0x989680;\n\t"
                 "@P bra WD_%=;\n\t"
                 "bra WL_%=;\n\t"
                 "WD_%=:\n\t}"
                 :: "r"(addr), "r"(parity) : "memory");
}
// 1D bulk copy gmem->smem, completion via mbarrier complete_tx
__device__ __forceinline__ void bulkcp(uint dst, const void* src, uint bytes,
                                       uint mbar) {
    asm volatile(
        "cp.async.bulk.shared::cluster.global.mbarrier::complete_tx::bytes "
        "[%0], [%1], %2, [%3];"
        :: "r"(dst), "l"(src), "r"(bytes), "r"(mbar) : "memory");
}
__device__ __forceinline__ void ldsm4(uint& r0, uint& r1, uint& r2, uint& r3,
                                      uint addr) {
    asm volatile("ldmatrix.sync.aligned.m8n8.x4.shared.b16 {%0,%1,%2,%3}, [%4];"
                 : "=r"(r0), "=r"(r1), "=r"(r2), "=r"(r3) : "r"(addr));
}
__device__ __forceinline__ void mma16816(float* c, const uint* a, const uint* b) {
    asm volatile("mma.sync.aligned.m16n8k16.row.col.f32.bf16.bf16.f32 "
                 "{%0,%1,%2,%3}, {%4,%5,%6,%7}, {%8,%9}, {%0,%1,%2,%3};"
                 : "+f"(c[0]), "+f"(c[1]), "+f"(c[2]), "+f"(c[3])
                 : "r"(a[0]), "r"(a[1]), "r"(a[2]), "r"(a[3]),
                   "r"(b[0]), "r"(b[1]));
}
__device__ __forceinline__ uint packbf(float x, float y) {
    __nv_bfloat162 h = __floats2bfloat162_rn(x, y);
    return *reinterpret_cast<uint*>(&h);
}

// =====================================================================
// launch #1: transpose z [B=16, C=256, HW=1024] -> zt [n][c]  AND emit
// g_zbf (bf16, ldmatrix-swizzle baked) directly from the smem tile.
// Swizzle: 16B chunk ci of row n lands at byte n*512 + ((ci ^ (n&7))<<4).
// =====================================================================
__global__ void k_transpose(const float* __restrict__ z) {
    __shared__ float t[32][33];
    int b = blockIdx.z, c0 = blockIdx.y * 32, hw0 = blockIdx.x * 32;
    float* zt = (float*)g_zt4;
#pragma unroll
    for (int r = 0; r < 4; r++) {
        int c = c0 + threadIdx.y + 8 * r;
        t[threadIdx.y + 8 * r][threadIdx.x] =
            z[((size_t)(b * 256 + c)) * 1024 + hw0 + threadIdx.x];
    }
    __syncthreads();
#pragma unroll
    for (int r = 0; r < 4; r++) {
        int hw = hw0 + threadIdx.y + 8 * r;
        zt[((size_t)(b * 1024 + hw)) * 256 + c0 + threadIdx.x] =
            t[threadIdx.x][threadIdx.y + 8 * r];
    }
    // fused bf16 + baked-swizzle emission (128 threads, 16B each)
    int flat = threadIdx.y * 32 + threadIdx.x;
    if (flat < 128) {
        int nl = flat >> 2, ch = flat & 3;
        int n = b * 1024 + hw0 + nl;
        uint4 o;
        o.x = packbf(t[ch * 8 + 0][nl], t[ch * 8 + 1][nl]);
        o.y = packbf(t[ch * 8 + 2][nl], t[ch * 8 + 3][nl]);
        o.z = packbf(t[ch * 8 + 4][nl], t[ch * 8 + 5][nl]);
        o.w = packbf(t[ch * 8 + 6][nl], t[ch * 8 + 7][nl]);
        int ci = (c0 >> 3) + ch;
        *(uint4*)((char*)g_zbf + (size_t)n * 512 + (uint)((ci ^ (n & 7)) << 4)) = o;
    }
}

// =====================================================================
// launch #2: fused prep.
// blocks [0,512): z row-norms (strictly sequential fp32 adds, XLA
// semantics); [512,1024): codebook row-norms; [1024,3072): codebook
// fp32->bf16 with baked swizzle (+ first 64 of those zero g_ccnt).
// =====================================================================
__global__ void k_prep2(const float* __restrict__ cb) {
    if (blockIdx.x < 1024) {
        __shared__ float s[32 * 257];
        const int zpart = blockIdx.x < 512;
        const int base = (zpart ? blockIdx.x : blockIdx.x - 512) * 32;
        const float* src = zpart ? (const float*)g_zt4 : cb;
        float* dst = zpart ? g_zn2 : g_ce;
        for (int off = threadIdx.x; off < 32 * 256; off += 256) {
            int r = off >> 8, d = off & 255;
            s[r * 257 + d] = src[(size_t)base * 256 + off];
        }
        __syncthreads();
        if (threadIdx.x < 32) {
            const float* row = &s[threadIdx.x * 257];
            float a = 0.f;
            for (int d = 0; d < 256; ++d) {
                float v = row[d];
                a = __fadd_rn(a, __fmul_rn(v, v));
            }
            dst[base + threadIdx.x] = a;
        }
    } else {
        int t = (blockIdx.x - 1024) * 256 + threadIdx.x;
        const float4* src = (const float4*)cb;
        float4 a = src[2 * t], b2 = src[2 * t + 1];
        uint4 o;
        o.x = packbf(a.x, a.y); o.y = packbf(a.z, a.w);
        o.z = packbf(b2.x, b2.y); o.w = packbf(b2.z, b2.w);
        int c = t >> 5, ci = t & 31;
        *(uint4*)((char*)g_cbbf + (size_t)c * 512 + (uint)((ci ^ (c & 7)) << 4)) = o;
        if (blockIdx.x < 1024 + 64)
            g_ccnt[(blockIdx.x - 1024) * 256 + threadIdx.x] = 0;  // per replay
    }
}

// =====================================================================
// launch #3: bf16 mma.sync GEMM + approx argmin + candidate collection.
// (unchanged from R15 — 128 CTAs, 16 warps, A-in-regs, 3-buf B ring,
//  barrier-free mainloop, s' = ce - 2g window with rare-append guard)
// =====================================================================
#define SM_A   0u
#define SM_B   131072u
#define SM_BAR 229376u
#define SMEM_BYTES 229440

__global__ __launch_bounds__(512, 1) void k_mma_argmin() {
    extern __shared__ char smem[];
    const uint sb = smem_u32(smem);
    const int tid = threadIdx.x, lane = tid & 31, wid = tid >> 5;
    const int mblk = blockIdx.x >> 1, nhalf = blockIdx.x & 1;
    const int rowbase = mblk * 256, codebase0 = nhalf * 8192;

    const uint mbA = sb + SM_BAR;        // A full
    const uint mbF = sb + SM_BAR + 8;    // full[3]     at +8,+16,+24
    const uint mbC = sb + SM_BAR + 32;   // consumed[3] at +32,+40,+48

    if (tid == 0) {
        mbar_init(mbA, 1);
#pragma unroll
        for (int b = 0; b < 3; b++) {
            mbar_init(mbF + 8u * b, 1);
            mbar_init(mbC + 8u * b, 16);
        }
    }
    __syncthreads();   // mbar init visible before any wait/bulk
    if (tid == 0) {
        mbar_expect_tx(mbA, 131072u);
        bulkcp(sb + SM_A, (const char*)g_zbf + (size_t)rowbase * 512, 131072u, mbA);
#pragma unroll
        for (int b = 0; b < 3; b++) {
            mbar_expect_tx(mbF + 8u * b, 32768u);
            bulkcp(sb + SM_B + 32768u * b,
                   (const char*)g_cbbf + (size_t)(codebase0 + 64 * b) * 512,
                   32768u, mbF + 8u * b);
        }
    }

    // ---- per-thread geometry ----
    const int rowA = (lane & 7) + ((lane >> 3) & 1) * 8;
    const int aK = lane >> 4;
    const int rA = wid * 16 + rowA;
    const uint aAddr = sb + SM_A + (uint)rA * 512u;
    const int aSw = rA & 7;

    const int rowB = (lane & 7) + (lane >> 4) * 8;     // 0..15
    const int bK = (lane >> 3) & 1;
    const int bSw = rowB & 7;

    const int colq = (lane & 3) * 2;

    // ---- load ALL A fragments into registers (once) ----
    mbar_wait(mbA, 0);
    uint aF[16][4];
#pragma unroll
    for (int ks = 0; ks < 16; ++ks)
        ldsm4(aF[ks][0], aF[ks][1], aF[ks][2], aF[ks][3],
              aAddr + (uint)(((2 * ks + aK) ^ aSw) << 4));

    float minv[2] = { __int_as_float(0x7f800000), __int_as_float(0x7f800000) };

    for (int kt = 0; kt < 128; ++kt) {
        const int buf = kt - (kt / 3) * 3;       // kt % 3
        const uint par = (uint)(kt / 3) & 1u;
        mbar_wait(mbF + 8u * buf, par);

        float acc[8][4];
#pragma unroll
        for (int nf = 0; nf < 8; nf++)
#pragma unroll
            for (int v = 0; v < 4; v++) acc[nf][v] = 0.f;

        const uint bb = sb + SM_B + 32768u * buf + (uint)rowB * 512u;
#pragma unroll
        for (int ks = 0; ks < 16; ++ks) {
            const uint ch = (uint)(((2 * ks + bK) ^ bSw) << 4);
            uint b0[4], b1[4], b2[4], b3[4];
            ldsm4(b0[0], b0[1], b0[2], b0[3], bb + ch);
            ldsm4(b1[0], b1[1], b1[2], b1[3], bb + 16u * 512u + ch);
            ldsm4(b2[0], b2[1], b2[2], b2[3], bb + 32u * 512u + ch);
            ldsm4(b3[0], b3[1], b3[2], b3[3], bb + 48u * 512u + ch);
            mma16816(acc[0], aF[ks], b0);
            mma16816(acc[1], aF[ks], b0 + 2);
            mma16816(acc[2], aF[ks], b1);
            mma16816(acc[3], aF[ks], b1 + 2);
            mma16816(acc[4], aF[ks], b2);
            mma16816(acc[5], aF[ks], b2 + 2);
            mma16816(acc[6], aF[ks], b3);
            mma16816(acc[7], aF[ks], b3 + 2);
        }

        // ---- epilogue: s' = ce - 2g, row-min via shfl, rare appends ----
        const int ctile = codebase0 + kt * 64;
        float ce_r[16];
#pragma unroll
        for (int nf = 0; nf < 8; nf++) {
            float2 cc = __ldg((const float2*)&g_ce[ctile + nf * 8 + colq]);
            ce_r[nf * 2 + 0] = cc.x;
            ce_r[nf * 2 + 1] = cc.y;
        }

#pragma unroll
        for (int h = 0; h < 2; h++) {
            float tmin = __int_as_float(0x7f800000);
#pragma unroll
            for (int nf = 0; nf < 8; nf++)
#pragma unroll
                for (int q = 0; q < 2; q++) {
                    float s = __fmaf_rn(-2.f, acc[nf][h * 2 + q],
                                        ce_r[nf * 2 + q]);
                    acc[nf][h * 2 + q] = s;
                    tmin = fminf(tmin, s);
                }
            // 4-lane row-group reduction (lanes differing in bits 0,1)
            tmin = fminf(tmin, __shfl_xor_sync(0xffffffffu, tmin, 1));
            tmin = fminf(tmin, __shfl_xor_sync(0xffffffffu, tmin, 2));
            const float mwin = (kt == 0 ? tmin : minv[h]) + WINDOW;
            if (tmin < mwin) {            // rare: this tile touches the window
                const int grow = rowbase + wid * 16 + (lane >> 2) + 8 * h;
#pragma unroll
                for (int nf = 0; nf < 8; nf++)
#pragma unroll
                    for (int q = 0; q < 2; q++) {
                        if (acc[nf][h * 2 + q] < mwin) {
                            int pos = atomicAdd(&g_ccnt[grow], 1);
                            if (pos < KCAND)
                                g_cand[grow * KCAND + pos] =
                                    ctile + nf * 8 + colq + q;
                        }
                    }
            }
            minv[h] = fminf(minv[h], tmin);
        }

        // ---- ring bookkeeping (no CTA barrier) ----
        if (lane == 0) mbar_arrive(mbC + 8u * buf);
        if (tid == 0 && kt + 3 < 128) {
            mbar_wait(mbC + 8u * buf, par);    // all 16 warps done with tile kt
            mbar_expect_tx(mbF + 8u * buf, 32768u);
            bulkcp(sb + SM_B + 32768u * buf,
                   (const char*)g_cbbf + (size_t)(codebase0 + (kt + 3) * 64) * 512,
                   32768u, mbF + 8u * buf);
        }
    }
}

// =====================================================================
// launch #4: exact fp32 rescore of candidates + FUSED output gather.
// One warp per row; grid 4096 x 128 threads; __launch_bounds__(128,8)
// caps regs at 64 -> 32 resident warps/SM (was 255 regs / occ 10.7%).
// Rescore arithmetic is BIT-IDENTICAL to R15 (lo/hi fma ascending d,
// g = fadd(lo,hi), s = fl(fl(zn+ce) - 2g), lowest-index tie-break).
// After the butterfly reduction every lane holds bi; the warp gathers
// codebook[bi] (64 float4, 2 per lane) straight into d_out and lane 0
// writes the idx float. Replaces the separate k_gather launch.
// =====================================================================
__global__ __launch_bounds__(128, 8) void k_rescore(const float* __restrict__ cb,
                                                    float* __restrict__ out,
                                                    int write_idx) {
    const int gw = (blockIdx.x * 128 + threadIdx.x) >> 5;
    const int lane = threadIdx.x & 31;
    const float4* zr4 = (const float4*)((const float*)g_zt4 + (size_t)gw * 256);
    const float zn = g_zn2[gw];
    const int cnt = g_ccnt[gw];
    float s = __int_as_float(0x7f800000);
    int bi = 0x7fffffff;
    if (cnt <= KCAND) {
        for (int ci = lane; ci < cnt; ci += 32) {
            int c = g_cand[gw * KCAND + ci];
            const float4* er4 = (const float4*)(cb + (size_t)c * 256);
            float lo = 0.f, hi = 0.f;
#pragma unroll 4
            for (int d4 = 0; d4 < 64; ++d4) {
                float4 zv = zr4[d4];
                float4 ev = __ldg(&er4[d4]);
                lo = __fmaf_rn(zv.x, ev.x, lo);
                hi = __fmaf_rn(zv.y, ev.y, hi);
                lo = __fmaf_rn(zv.z, ev.z, lo);
                hi = __fmaf_rn(zv.w, ev.w, hi);
            }
            float g = __fadd_rn(lo, hi);
            float sc = __fmaf_rn(-2.0f, g, __fadd_rn(zn, g_ce[c]));
            if (sc < s || (sc == s && c < bi)) { s = sc; bi = c; }
        }
    } else {
        // overflow fallback: exact full-row scan (expected never)
        for (int c = lane; c < KCODES; c += 32) {
            const float4* er4 = (const float4*)(cb + (size_t)c * 256);
            float lo = 0.f, hi = 0.f;
#pragma unroll 2
            for (int d4 = 0; d4 < 64; ++d4) {
                float4 zv = zr4[d4];
                float4 ev = __ldg(&er4[d4]);
                lo = __fmaf_rn(zv.x, ev.x, lo);
                hi = __fmaf_rn(zv.y, ev.y, hi);
                lo = __fmaf_rn(zv.z, ev.z, lo);
                hi = __fmaf_rn(zv.w, ev.w, hi);
            }
            float g = __fadd_rn(lo, hi);
            float sc = __fmaf_rn(-2.0f, g, __fadd_rn(zn, g_ce[c]));
            if (sc < s || (sc == s && c < bi)) { s = sc; bi = c; }
        }
    }
#pragma unroll
    for (int o = 16; o; o >>= 1) {
        float s2 = __shfl_xor_sync(0xffffffffu, s, o);
        int b2 = __shfl_xor_sync(0xffffffffu, bi, o);
        if (s2 < s || (s2 == s && b2 < bi)) { s = s2; bi = b2; }
    }
    // fused gather: all lanes hold bi after the butterfly
    const float4* src = (const float4*)(cb + (size_t)bi * 256);
    float4* dst = (float4*)(out + (size_t)gw * 256);
    dst[lane]      = __ldg(&src[lane]);
    dst[lane + 32] = __ldg(&src[lane + 32]);
    if (write_idx && lane == 0) out[NZQ + gw] = (float)bi;
}

// =====================================================================
extern "C" void kernel_launch(void* const* d_in, const int* in_sizes, int n_in,
                              void* d_out, int out_size) {
    const float* z  = (const float*)d_in[0];
    const float* cb = (const float*)d_in[1];

    k_transpose<<<dim3(32, 8, 16), dim3(32, 8)>>>(z);
    k_prep2<<<3072, 256>>>(cb);

    cudaFuncSetAttribute(k_mma_argmin, cudaFuncAttributeMaxDynamicSharedMemorySize,
                         SMEM_BYTES);
    k_mma_argmin<<<128, 512, SMEM_BYTES>>>();

    int write_idx = (out_size >= NZQ + NROWS) ? 1 : 0;
    k_rescore<<<4096, 128>>>(cb, (float*)d_out, write_idx);
}

// round 17
// speedup vs baseline: 1.4760x; 1.0432x over previous
#include <cuda_runtime.h>
#include <cuda_bf16.h>
#include <cstdint>

// VectorQuantizer: z[16,256,32,32] fp32, codebook[16384,256] fp32
// out: z_q [16,32,32,256] flattened (4,194,304 floats) then idx (16384) as float.

#define NROWS 16384
#define KCODES 16384
#define NZQ (16384*256)
#define KCAND 64
#define WINDOW 2.0e-4f
#define NSTAGE 8
#define ESTRIDE 65   // float4 units: 65*16 = 1040 B row pitch (bank spread)

typedef unsigned int uint;

// ---- scratch (device globals; no allocation allowed) ----
__device__ float4        g_zt4[NROWS * 64];      // z transposed [N][256] fp32, 16 MB
__device__ float         g_zn2[NROWS];
__device__ float         g_ce[KCODES];
__device__ __nv_bfloat16 g_zbf[NROWS * 256];     // bf16, ldmatrix-swizzle baked, 8 MB
__device__ __nv_bfloat16 g_cbbf[KCODES * 256];   // bf16, ldmatrix-swizzle baked, 8 MB
__device__ int           g_cand[NROWS * KCAND];  // 4 MB
__device__ int           g_ccnt[NROWS];

// =====================================================================
// helpers (baseline sm_90 PTX only: compiles under compute_103 virtual)
// =====================================================================
__device__ __forceinline__ uint smem_u32(const void* p) {
    uint a;
    asm("{ .reg .u64 t; cvta.to.shared.u64 t, %1; cvt.u32.u64 %0, t; }"
        : "=r"(a) : "l"(p));
    return a;
}
__device__ __forceinline__ void mbar_init(uint addr, uint cnt) {
    asm volatile("mbarrier.init.shared.b64 [%0], %1;" :: "r"(addr), "r"(cnt) : "memory");
}
__device__ __forceinline__ void mbar_arrive(uint addr) {
    asm volatile("mbarrier.arrive.shared.b64 _, [%0];" :: "r"(addr) : "memory");
}
__device__ __forceinline__ void mbar_expect_tx(uint addr, uint tx) {
    asm volatile("mbarrier.arrive.expect_tx.shared.b64 _, [%0], %1;"
                 :: "r"(addr), "r"(tx) : "memory");
}
__device__ __forceinline__ void mbar_wait(uint addr, uint parity) {
    asm volatile("{\n\t.reg .pred P;\n\t"
                 "WL_%=:\n\t"
                 "mbarrier.try_wait.parity.acquire.cta.shared::cta.b64 P, [%0], %1, 0x989680;\n\t"
                 "@P bra WD_%=;\n\t"
                 "bra WL_%=;\n\t"
                 "WD_%=:\n\t}"
                 :: "r"(addr), "r"(parity) : "memory");
}
// 1D bulk copy gmem->smem, completion via mbarrier complete_tx
__device__ __forceinline__ void bulkcp(uint dst, const void* src, uint bytes,
                                       uint mbar) {
    asm volatile(
        "cp.async.bulk.shared::cluster.global.mbarrier::complete_tx::bytes "
        "[%0], [%1], %2, [%3];"
        :: "r"(dst), "l"(src), "r"(bytes), "r"(mbar) : "memory");
}
__device__ __forceinline__ void ldsm4(uint& r0, uint& r1, uint& r2, uint& r3,
                                      uint addr) {
    asm volatile("ldmatrix.sync.aligned.m8n8.x4.shared.b16 {%0,%1,%2,%3}, [%4];"
                 : "=r"(r0), "=r"(r1), "=r"(r2), "=r"(r3) : "r"(addr));
}
__device__ __forceinline__ void mma16816(float* c, const uint* a, const uint* b) {
    asm volatile("mma.sync.aligned.m16n8k16.row.col.f32.bf16.bf16.f32 "
                 "{%0,%1,%2,%3}, {%4,%5,%6,%7}, {%8,%9}, {%0,%1,%2,%3};"
                 : "+f"(c[0]), "+f"(c[1]), "+f"(c[2]), "+f"(c[3])
                 : "r"(a[0]), "r"(a[1]), "r"(a[2]), "r"(a[3]),
                   "r"(b[0]), "r"(b[1]));
}
__device__ __forceinline__ uint packbf(float x, float y) {
    __nv_bfloat162 h = __floats2bfloat162_rn(x, y);
    return *reinterpret_cast<uint*>(&h);
}

// =====================================================================
// launch #1: transpose z [B=16, C=256, HW=1024] -> zt [n][c]  AND emit
// g_zbf (bf16, ldmatrix-swizzle baked) directly from the smem tile.
// Swizzle: 16B chunk ci of row n lands at byte n*512 + ((ci ^ (n&7))<<4).
// =====================================================================
__global__ void k_transpose(const float* __restrict__ z) {
    __shared__ float t[32][33];
    int b = blockIdx.z, c0 = blockIdx.y * 32, hw0 = blockIdx.x * 32;
    float* zt = (float*)g_zt4;
#pragma unroll
    for (int r = 0; r < 4; r++) {
        int c = c0 + threadIdx.y + 8 * r;
        t[threadIdx.y + 8 * r][threadIdx.x] =
            z[((size_t)(b * 256 + c)) * 1024 + hw0 + threadIdx.x];
    }
    __syncthreads();
#pragma unroll
    for (int r = 0; r < 4; r++) {
        int hw = hw0 + threadIdx.y + 8 * r;
        zt[((size_t)(b * 1024 + hw)) * 256 + c0 + threadIdx.x] =
            t[threadIdx.x][threadIdx.y + 8 * r];
    }
    // fused bf16 + baked-swizzle emission (128 threads, 16B each)
    int flat = threadIdx.y * 32 + threadIdx.x;
    if (flat < 128) {
        int nl = flat >> 2, ch = flat & 3;
        int n = b * 1024 + hw0 + nl;
        uint4 o;
        o.x = packbf(t[ch * 8 + 0][nl], t[ch * 8 + 1][nl]);
        o.y = packbf(t[ch * 8 + 2][nl], t[ch * 8 + 3][nl]);
        o.z = packbf(t[ch * 8 + 4][nl], t[ch * 8 + 5][nl]);
        o.w = packbf(t[ch * 8 + 6][nl], t[ch * 8 + 7][nl]);
        int ci = (c0 >> 3) + ch;
        *(uint4*)((char*)g_zbf + (size_t)n * 512 + (uint)((ci ^ (n & 7)) << 4)) = o;
    }
}

// =====================================================================
// launch #2: fused prep.
// blocks [0,512): z row-norms (strictly sequential fp32 adds, XLA
// semantics); [512,1024): codebook row-norms; [1024,3072): codebook
// fp32->bf16 with baked swizzle (+ first 64 of those zero g_ccnt).
// =====================================================================
__global__ void k_prep2(const float* __restrict__ cb) {
    if (blockIdx.x < 1024) {
        __shared__ float s[32 * 257];
        const int zpart = blockIdx.x < 512;
        const int base = (zpart ? blockIdx.x : blockIdx.x - 512) * 32;
        const float* src = zpart ? (const float*)g_zt4 : cb;
        float* dst = zpart ? g_zn2 : g_ce;
        for (int off = threadIdx.x; off < 32 * 256; off += 256) {
            int r = off >> 8, d = off & 255;
            s[r * 257 + d] = src[(size_t)base * 256 + off];
        }
        __syncthreads();
        if (threadIdx.x < 32) {
            const float* row = &s[threadIdx.x * 257];
            float a = 0.f;
            for (int d = 0; d < 256; ++d) {
                float v = row[d];
                a = __fadd_rn(a, __fmul_rn(v, v));
            }
            dst[base + threadIdx.x] = a;
        }
    } else {
        int t = (blockIdx.x - 1024) * 256 + threadIdx.x;
        const float4* src = (const float4*)cb;
        float4 a = src[2 * t], b2 = src[2 * t + 1];
        uint4 o;
        o.x = packbf(a.x, a.y); o.y = packbf(a.z, a.w);
        o.z = packbf(b2.x, b2.y); o.w = packbf(b2.z, b2.w);
        int c = t >> 5, ci = t & 31;
        *(uint4*)((char*)g_cbbf + (size_t)c * 512 + (uint)((ci ^ (c & 7)) << 4)) = o;
        if (blockIdx.x < 1024 + 64)
            g_ccnt[(blockIdx.x - 1024) * 256 + threadIdx.x] = 0;  // per replay
    }
}

// =====================================================================
// launch #3: bf16 mma.sync GEMM + approx argmin + candidate collection.
// (unchanged from R15/R16 — 128 CTAs, 16 warps, A-in-regs, 3-buf B ring,
//  barrier-free mainloop, s' = ce - 2g window with rare-append guard)
// =====================================================================
#define SM_A   0u
#define SM_B   131072u
#define SM_BAR 229376u
#define SMEM_BYTES 229440

__global__ __launch_bounds__(512, 1) void k_mma_argmin() {
    extern __shared__ char smem[];
    const uint sb = smem_u32(smem);
    const int tid = threadIdx.x, lane = tid & 31, wid = tid >> 5;
    const int mblk = blockIdx.x >> 1, nhalf = blockIdx.x & 1;
    const int rowbase = mblk * 256, codebase0 = nhalf * 8192;

    const uint mbA = sb + SM_BAR;        // A full
    const uint mbF = sb + SM_BAR + 8;    // full[3]     at +8,+16,+24
    const uint mbC = sb + SM_BAR + 32;   // consumed[3] at +32,+40,+48

    if (tid == 0) {
        mbar_init(mbA, 1);
#pragma unroll
        for (int b = 0; b < 3; b++) {
            mbar_init(mbF + 8u * b, 1);
            mbar_init(mbC + 8u * b, 16);
        }
    }
    __syncthreads();   // mbar init visible before any wait/bulk
    if (tid == 0) {
        mbar_expect_tx(mbA, 131072u);
        bulkcp(sb + SM_A, (const char*)g_zbf + (size_t)rowbase * 512, 131072u, mbA);
#pragma unroll
        for (int b = 0; b < 3; b++) {
            mbar_expect_tx(mbF + 8u * b, 32768u);
            bulkcp(sb + SM_B + 32768u * b,
                   (const char*)g_cbbf + (size_t)(codebase0 + 64 * b) * 512,
                   32768u, mbF + 8u * b);
        }
    }

    // ---- per-thread geometry ----
    const int rowA = (lane & 7) + ((lane >> 3) & 1) * 8;
    const int aK = lane >> 4;
    const int rA = wid * 16 + rowA;
    const uint aAddr = sb + SM_A + (uint)rA * 512u;
    const int aSw = rA & 7;

    const int rowB = (lane & 7) + (lane >> 4) * 8;     // 0..15
    const int bK = (lane >> 3) & 1;
    const int bSw = rowB & 7;

    const int colq = (lane & 3) * 2;

    // ---- load ALL A fragments into registers (once) ----
    mbar_wait(mbA, 0);
    uint aF[16][4];
#pragma unroll
    for (int ks = 0; ks < 16; ++ks)
        ldsm4(aF[ks][0], aF[ks][1], aF[ks][2], aF[ks][3],
              aAddr + (uint)(((2 * ks + aK) ^ aSw) << 4));

    float minv[2] = { __int_as_float(0x7f800000), __int_as_float(0x7f800000) };

    for (int kt = 0; kt < 128; ++kt) {
        const int buf = kt - (kt / 3) * 3;       // kt % 3
        const uint par = (uint)(kt / 3) & 1u;
        mbar_wait(mbF + 8u * buf, par);

        float acc[8][4];
#pragma unroll
        for (int nf = 0; nf < 8; nf++)
#pragma unroll
            for (int v = 0; v < 4; v++) acc[nf][v] = 0.f;

        const uint bb = sb + SM_B + 32768u * buf + (uint)rowB * 512u;
#pragma unroll
        for (int ks = 0; ks < 16; ++ks) {
            const uint ch = (uint)(((2 * ks + bK) ^ bSw) << 4);
            uint b0[4], b1[4], b2[4], b3[4];
            ldsm4(b0[0], b0[1], b0[2], b0[3], bb + ch);
            ldsm4(b1[0], b1[1], b1[2], b1[3], bb + 16u * 512u + ch);
            ldsm4(b2[0], b2[1], b2[2], b2[3], bb + 32u * 512u + ch);
            ldsm4(b3[0], b3[1], b3[2], b3[3], bb + 48u * 512u + ch);
            mma16816(acc[0], aF[ks], b0);
            mma16816(acc[1], aF[ks], b0 + 2);
            mma16816(acc[2], aF[ks], b1);
            mma16816(acc[3], aF[ks], b1 + 2);
            mma16816(acc[4], aF[ks], b2);
            mma16816(acc[5], aF[ks], b2 + 2);
            mma16816(acc[6], aF[ks], b3);
            mma16816(acc[7], aF[ks], b3 + 2);
        }

        // ---- epilogue: s' = ce - 2g, row-min via shfl, rare appends ----
        const int ctile = codebase0 + kt * 64;
        float ce_r[16];
#pragma unroll
        for (int nf = 0; nf < 8; nf++) {
            float2 cc = __ldg((const float2*)&g_ce[ctile + nf * 8 + colq]);
            ce_r[nf * 2 + 0] = cc.x;
            ce_r[nf * 2 + 1] = cc.y;
        }

#pragma unroll
        for (int h = 0; h < 2; h++) {
            float tmin = __int_as_float(0x7f800000);
#pragma unroll
            for (int nf = 0; nf < 8; nf++)
#pragma unroll
                for (int q = 0; q < 2; q++) {
                    float s = __fmaf_rn(-2.f, acc[nf][h * 2 + q],
                                        ce_r[nf * 2 + q]);
                    acc[nf][h * 2 + q] = s;
                    tmin = fminf(tmin, s);
                }
            // 4-lane row-group reduction (lanes differing in bits 0,1)
            tmin = fminf(tmin, __shfl_xor_sync(0xffffffffu, tmin, 1));
            tmin = fminf(tmin, __shfl_xor_sync(0xffffffffu, tmin, 2));
            const float mwin = (kt == 0 ? tmin : minv[h]) + WINDOW;
            if (tmin < mwin) {            // rare: this tile touches the window
                const int grow = rowbase + wid * 16 + (lane >> 2) + 8 * h;
#pragma unroll
                for (int nf = 0; nf < 8; nf++)
#pragma unroll
                    for (int q = 0; q < 2; q++) {
                        if (acc[nf][h * 2 + q] < mwin) {
                            int pos = atomicAdd(&g_ccnt[grow], 1);
                            if (pos < KCAND)
                                g_cand[grow * KCAND + pos] =
                                    ctile + nf * 8 + colq + q;
                        }
                    }
            }
            minv[h] = fminf(minv[h], tmin);
        }

        // ---- ring bookkeeping (no CTA barrier) ----
        if (lane == 0) mbar_arrive(mbC + 8u * buf);
        if (tid == 0 && kt + 3 < 128) {
            mbar_wait(mbC + 8u * buf, par);    // all 16 warps done with tile kt
            mbar_expect_tx(mbF + 8u * buf, 32768u);
            bulkcp(sb + SM_B + 32768u * buf,
                   (const char*)g_cbbf + (size_t)(codebase0 + (kt + 3) * 64) * 512,
                   32768u, mbF + 8u * buf);
        }
    }
}

// =====================================================================
// launch #4: exact fp32 rescore + fused gather, SMEM-STAGED.
// R16's version was L1-wavefront bound (74.7% L1): each active lane
// walked a DIFFERENT codebook row, so every float4 load instruction
// produced ~#lanes scattered wavefronts. Fix: per warp (1 row), process
// candidates in batches of NSTAGE=8 — all 32 lanes COOPERATIVELY stage
// the 8 e-rows (coalesced 128B wavefronts) + the z-row into smem; then
// lanes 0..7 run their candidate's chain from smem (z reads broadcast,
// e reads stride-65-float4 -> distinct bank groups, 1 phase).
// Arithmetic is BIT-IDENTICAL to R15/R16: lo/hi fma ascending d,
// g = fadd(lo,hi), s = fl(fl(zn+ce) - 2g), lowest-index tie-break.
// Fused gather unchanged. Fallback full scan for cnt>KCAND unchanged.
// smem 37376 B/block -> 6 blocks (24 warps)/SM.
// =====================================================================
__global__ __launch_bounds__(128, 6) void k_rescore(const float* __restrict__ cb,
                                                    float* __restrict__ out,
                                                    int write_idx) {
    __shared__ float4 sZ[4][64];                 //  4 KB: one z row per warp
    __shared__ float4 sE[4][NSTAGE * ESTRIDE];   // 33.3 KB: 8 e-rows per warp
    const int wir = threadIdx.x >> 5;
    const int lane = threadIdx.x & 31;
    const int gw = blockIdx.x * 4 + wir;
    const float zn = g_zn2[gw];
    const int cnt = g_ccnt[gw];
    float4* zS = sZ[wir];
    float4* eS = sE[wir];

    // stage z row (cooperative, coalesced; broadcast-read later)
    {
        const float4* zr4 = (const float4*)((const float*)g_zt4 + (size_t)gw * 256);
        zS[lane]      = zr4[lane];
        zS[lane + 32] = zr4[lane + 32];
    }

    float s = __int_as_float(0x7f800000);
    int bi = 0x7fffffff;
    if (cnt <= KCAND) {
        for (int base = 0; base < cnt; base += NSTAGE) {
            const int nb = (cnt - base < NSTAGE) ? (cnt - base) : NSTAGE;
            __syncwarp();                         // prev chain done / zS ready
            for (int b = 0; b < nb; ++b) {
                int c = g_cand[gw * KCAND + base + b];      // broadcast load
                const float4* er4 = (const float4*)(cb + (size_t)c * 256);
                eS[b * ESTRIDE + lane]      = __ldg(&er4[lane]);
                eS[b * ESTRIDE + lane + 32] = __ldg(&er4[lane + 32]);
            }
            __syncwarp();                         // staging visible
            if (lane < nb) {
                const int c = g_cand[gw * KCAND + base + lane];
                const float4* ep = &eS[lane * ESTRIDE];
                float lo = 0.f, hi = 0.f;
#pragma unroll 8
                for (int d4 = 0; d4 < 64; ++d4) {
                    float4 zv = zS[d4];
                    float4 ev = ep[d4];
                    lo = __fmaf_rn(zv.x, ev.x, lo);
                    hi = __fmaf_rn(zv.y, ev.y, hi);
                    lo = __fmaf_rn(zv.z, ev.z, lo);
                    hi = __fmaf_rn(zv.w, ev.w, hi);
                }
                float g = __fadd_rn(lo, hi);
                float sc = __fmaf_rn(-2.0f, g, __fadd_rn(zn, g_ce[c]));
                if (sc < s || (sc == s && c < bi)) { s = sc; bi = c; }
            }
        }
    } else {
        // overflow fallback: exact full-row scan (expected never)
        const float4* zr4 = (const float4*)((const float*)g_zt4 + (size_t)gw * 256);
        for (int c = lane; c < KCODES; c += 32) {
            const float4* er4 = (const float4*)(cb + (size_t)c * 256);
            float lo = 0.f, hi = 0.f;
#pragma unroll 2
            for (int d4 = 0; d4 < 64; ++d4) {
                float4 zv = zr4[d4];
                float4 ev = __ldg(&er4[d4]);
                lo = __fmaf_rn(zv.x, ev.x, lo);
                hi = __fmaf_rn(zv.y, ev.y, hi);
                lo = __fmaf_rn(zv.z, ev.z, lo);
                hi = __fmaf_rn(zv.w, ev.w, hi);
            }
            float g = __fadd_rn(lo, hi);
            float sc = __fmaf_rn(-2.0f, g, __fadd_rn(zn, g_ce[c]));
            if (sc < s || (sc == s && c < bi)) { s = sc; bi = c; }
        }
    }
#pragma unroll
    for (int o = 16; o; o >>= 1) {
        float s2 = __shfl_xor_sync(0xffffffffu, s, o);
        int b2 = __shfl_xor_sync(0xffffffffu, bi, o);
        if (s2 < s || (s2 == s && b2 < bi)) { s = s2; bi = b2; }
    }
    // fused gather: all lanes hold bi after the butterfly
    const float4* src = (const float4*)(cb + (size_t)bi * 256);
    float4* dst = (float4*)(out + (size_t)gw * 256);
    dst[lane]      = __ldg(&src[lane]);
    dst[lane + 32] = __ldg(&src[lane + 32]);
    if (write_idx && lane == 0) out[NZQ + gw] = (float)bi;
}

// =====================================================================
extern "C" void kernel_launch(void* const* d_in, const int* in_sizes, int n_in,
                              void* d_out, int out_size) {
    const float* z  = (const float*)d_in[0];
    const float* cb = (const float*)d_in[1];

    k_transpose<<<dim3(32, 8, 16), dim3(32, 8)>>>(z);
    k_prep2<<<3072, 256>>>(cb);

    cudaFuncSetAttribute(k_mma_argmin, cudaFuncAttributeMaxDynamicSharedMemorySize,
                         SMEM_BYTES);
    k_mma_argmin<<<128, 512, SMEM_BYTES>>>();

    int write_idx = (out_size >= NZQ + NROWS) ? 1 : 0;
    k_rescore<<<4096, 128>>>(cb, (float*)d_out, write_idx);
}